// round 15
// baseline (speedup 1.0000x reference)
#include <cuda_runtime.h>
#include <cuda_bf16.h>
#include <stdint.h>
#include <math.h>

// ---------------------------------------------------------------------------
// CharRNN on GB300 (sm_103 baseline PTX -> warp HMMA mma.sync bf16x3).
// R13: software-pipelined fragments. R11/R13 showed LDSM and MMA serialize
// within each warp (tensor 31.6%, step = tensor + LDSM + chain). Now each
// k16's 8 ldmatrix.x4 are issued BEFORE the previous k16's 24 MMAs retire
// (double-buffered register fragments), overlapping the shared-mem crossbar
// with the tensor pipe. Same for the xin/logits HMMA kernel.
// h_{t+1} = h_t + (h_t @ G^T) + dt*xin[t],  G = dt*(Wh - Wh^T - diff*I)
// ---------------------------------------------------------------------------

#define SEQ    1024
#define BATCH  128
#define HID    2048
#define EMB    512
#define VOCAB  50257
#define LDL    50260
#define DT     0.01f
#define DIFF   0.001f
#define NCTA   128
#define NGRP   32

// recurrence smem (bytes)
#define SM_B_HI   0
#define SM_B_LO   66560
#define SM_A_HI0  133120
#define SM_A_LO0  151552
#define SM_A_HI1  169984
#define SM_A_LO1  188416
#define SM_TOTAL  206848

// generic hmma gemm smem
#define GM_A_HI  0
#define GM_A_LO  34816
#define GM_B_HI  69632
#define GM_B_LO  87040
#define GM_TOTAL 104448

// scratch
__device__ float g_xin[(size_t)SEQ * BATCH * HID];
__device__ float g_weff[(size_t)HID * HID];          // G = dt*(Wh-Wh^T-diff I)
__device__ float g_h[2][BATCH * HID];                // fp32 carry (ping-pong)
__device__ __nv_bfloat16 g_hbf_hi[2][BATCH * HID];   // bf16 hi of h
__device__ __nv_bfloat16 g_hbf_lo[2][BATCH * HID];   // bf16 lo of h
__device__ float g_acc[4][BATCH * HID];              // split-K partials
__device__ float g_logits[(size_t)BATCH * LDL];
__device__ unsigned g_mma_cnt[NGRP];                 // partials of group ready
__device__ unsigned g_red_cnt[NGRP];                 // h cols of group ready

// ---------------------------------------------------------------------------
__device__ __forceinline__ uint32_t smem_u32(const void* p) {
    uint32_t a;
    asm("{ .reg .u64 t; cvta.to.shared.u64 t, %1; cvt.u32.u64 %0, t; }"
        : "=r"(a) : "l"(p));
    return a;
}

#define LDSM_X4(r, addr) \
    asm volatile("ldmatrix.sync.aligned.m8n8.x4.shared.b16 {%0,%1,%2,%3}, [%4];" \
        : "=r"((r)[0]), "=r"((r)[1]), "=r"((r)[2]), "=r"((r)[3]) \
        : "r"(addr))

#define MMA16816(c, a, b) \
    asm volatile("mma.sync.aligned.m16n8k16.row.col.f32.bf16.bf16.f32 " \
        "{%0,%1,%2,%3}, {%4,%5,%6,%7}, {%8,%9}, {%0,%1,%2,%3};" \
        : "+f"((c)[0]), "+f"((c)[1]), "+f"((c)[2]), "+f"((c)[3]) \
        : "r"((a)[0]), "r"((a)[1]), "r"((a)[2]), "r"((a)[3]), \
          "r"((b)[0]), "r"((b)[1]))

#define CP_ASYNC16(dst, src) \
    asm volatile("cp.async.cg.shared.global [%0], [%1], 16;" \
        :: "r"(dst), "l"(src) : "memory")
#define CP_COMMIT() asm volatile("cp.async.commit_group;" ::: "memory")
#define CP_WAIT0()  asm volatile("cp.async.wait_group 0;" ::: "memory")

__device__ __forceinline__ void spin_ge(const unsigned* p, unsigned thr) {
    while (*(volatile const unsigned*)p < thr) { }
}

// fp32 -> bf16 hi/lo pair (packed as 2 x uint32 of bf16x2)
__device__ __forceinline__ void split_bf16x4(float4 v, uint2& hi, uint2& lo) {
    __nv_bfloat162 h01 = __float22bfloat162_rn(make_float2(v.x, v.y));
    __nv_bfloat162 h23 = __float22bfloat162_rn(make_float2(v.z, v.w));
    float2 f01 = __bfloat1622float2(h01);
    float2 f23 = __bfloat1622float2(h23);
    __nv_bfloat162 l01 = __float22bfloat162_rn(make_float2(v.x - f01.x, v.y - f01.y));
    __nv_bfloat162 l23 = __float22bfloat162_rn(make_float2(v.z - f23.x, v.w - f23.y));
    hi = make_uint2(*(uint32_t*)&h01, *(uint32_t*)&h23);
    lo = make_uint2(*(uint32_t*)&l01, *(uint32_t*)&l23);
}

// 6 bf16x3 MMAs for one (m32 x n32) accumulator set from fragment arrays.
// fa: [ah0 ah1 al0 al1] x4 regs each; fb: [bh(8) bl(8)].
#define MMA_SET(cacc, fa, fb) do { \
    _Pragma("unroll") \
    for (int j_ = 0; j_ < 4; j_++) { \
        MMA16816((cacc)[0][j_], (fa) + 0,  (fb) + j_ * 2); \
        MMA16816((cacc)[1][j_], (fa) + 4,  (fb) + j_ * 2); \
        MMA16816((cacc)[0][j_], (fa) + 0,  (fb) + 8 + j_ * 2); \
        MMA16816((cacc)[1][j_], (fa) + 4,  (fb) + 8 + j_ * 2); \
        MMA16816((cacc)[0][j_], (fa) + 8,  (fb) + j_ * 2); \
        MMA16816((cacc)[1][j_], (fa) + 12, (fb) + j_ * 2); \
    } \
} while (0)

// ---------------------------------------------------------------------------
__global__ void build_weff_kernel(const float* __restrict__ Wh) {
    int idx = blockIdx.x * blockDim.x + threadIdx.x;
    if (idx < HID * HID) {
        int i = idx / HID, j = idx % HID;
        float v = Wh[idx] - Wh[j * HID + i];
        if (i == j) v -= DIFF;
        g_weff[idx] = DT * v;
    }
}

__global__ void init_h_kernel(const float* __restrict__ h0) {
    int i = blockIdx.x * blockDim.x + threadIdx.x;
    if (i < NGRP) { g_mma_cnt[i] = 0u; g_red_cnt[i] = 0u; }  // replay reset
    if (i < BATCH * HID) {
        float v = h0[i];
        g_h[0][i] = v;
        __nv_bfloat16 hi = __float2bfloat16_rn(v);
        g_hbf_hi[0][i] = hi;
        g_hbf_lo[0][i] = __float2bfloat16_rn(v - __bfloat162float(hi));
    }
}

// ---------------------------------------------------------------------------
// Generic NT HMMA GEMM (bf16x3), fragment-pipelined.
// ---------------------------------------------------------------------------
template <bool GATHER, bool HAS_BIAS>
__global__ __launch_bounds__(256) void hmma_nt_kernel(
    const float* __restrict__ A, const int* __restrict__ gidx,
    const float* __restrict__ B, const float* __restrict__ bias,
    float* __restrict__ C, int N, int K, int ldc)
{
    extern __shared__ char sm[];
    const uint32_t smb = smem_u32(sm);
    const int tid = threadIdx.x, wid = tid >> 5, lane = tid & 31;
    const int m0 = blockIdx.y * 128;
    const int n0 = blockIdx.x * 64;

    const int mw = (wid >> 1) * 32;
    const int nw = (wid & 1) * 32;
    const uint32_t a_off0 = (uint32_t)(mw + (lane & 15)) * 272
                          + ((lane & 16) ? 16u : 0u);
    const uint32_t a_off1 = a_off0 + 16u * 272u;
    const uint32_t b_row  = (uint32_t)((lane & 7) + ((lane & 16) ? 8 : 0));
    const uint32_t b_koff = (lane & 8) ? 16u : 0u;
    const uint32_t b_off0 = (uint32_t)(nw + b_row) * 272 + b_koff;
    const uint32_t b_off1 = (uint32_t)(nw + 16 + b_row) * 272 + b_koff;

    float c[2][4][4];
    #pragma unroll
    for (int i = 0; i < 2; i++)
        #pragma unroll
        for (int j = 0; j < 4; j++)
            #pragma unroll
            for (int q = 0; q < 4; q++) c[i][j][q] = 0.f;

#define GM_LD_FRAGS(fa, fb, kkv) do { \
    const uint32_t ak_ = (uint32_t)((kkv) * 32); \
    LDSM_X4((fa) + 0,  smb + GM_A_HI + a_off0 + ak_); \
    LDSM_X4((fa) + 4,  smb + GM_A_HI + a_off1 + ak_); \
    LDSM_X4((fa) + 8,  smb + GM_A_LO + a_off0 + ak_); \
    LDSM_X4((fa) + 12, smb + GM_A_LO + a_off1 + ak_); \
    LDSM_X4((fb) + 0,  smb + GM_B_HI + b_off0 + ak_); \
    LDSM_X4((fb) + 4,  smb + GM_B_HI + b_off1 + ak_); \
    LDSM_X4((fb) + 8,  smb + GM_B_LO + b_off0 + ak_); \
    LDSM_X4((fb) + 12, smb + GM_B_LO + b_off1 + ak_); \
} while (0)

    for (int kc = 0; kc < K; kc += 128) {
        __syncthreads();   // previous chunk fully consumed
        // stage A chunk: 128 rows x 128 cols
        for (int i = tid; i < 4096; i += 256) {
            int r = i >> 5, c4 = (i & 31) << 2;
            const float* arow = GATHER
                ? A + (size_t)__ldg(gidx + m0 + r) * K
                : A + (size_t)(m0 + r) * K;
            float4 v = *(const float4*)(arow + kc + c4);
            uint2 hi, lo;
            split_bf16x4(v, hi, lo);
            uint32_t off = (uint32_t)(r * 272 + c4 * 2);
            *(uint2*)(sm + GM_A_HI + off) = hi;
            *(uint2*)(sm + GM_A_LO + off) = lo;
        }
        // stage B chunk: 64 rows x 128 cols, zero-pad n >= N
        for (int i = tid; i < 2048; i += 256) {
            int r = i >> 5, c4 = (i & 31) << 2;
            int n = n0 + r;
            float4 v = (n < N) ? *(const float4*)(B + (size_t)n * K + kc + c4)
                               : make_float4(0.f, 0.f, 0.f, 0.f);
            uint2 hi, lo;
            split_bf16x4(v, hi, lo);
            uint32_t off = (uint32_t)(r * 272 + c4 * 2);
            *(uint2*)(sm + GM_B_HI + off) = hi;
            *(uint2*)(sm + GM_B_LO + off) = lo;
        }
        __syncthreads();

        uint32_t fa[2][16], fb[2][16];
        GM_LD_FRAGS(fa[0], fb[0], 0);
        #pragma unroll
        for (int kk = 0; kk < 8; kk++) {
            const int cs = kk & 1;
            if (kk < 7) GM_LD_FRAGS(fa[cs ^ 1], fb[cs ^ 1], kk + 1);
            MMA_SET(c, fa[cs], fb[cs]);
        }
    }
#undef GM_LD_FRAGS

    // epilogue: bias + guarded store
    #pragma unroll
    for (int i = 0; i < 2; i++) {
        int row = m0 + mw + i * 16 + (lane >> 2);
        #pragma unroll
        for (int j = 0; j < 4; j++) {
            int col = n0 + nw + j * 8 + (lane & 3) * 2;
            if (col < N) {
                float b0 = HAS_BIAS ? bias[col] : 0.f;
                C[(size_t)row * ldc + col]       = c[i][j][0] + b0;
                C[(size_t)(row + 8) * ldc + col] = c[i][j][2] + b0;
            }
            if (col + 1 < N) {
                float b1 = HAS_BIAS ? bias[col + 1] : 0.f;
                C[(size_t)row * ldc + col + 1]       = c[i][j][1] + b1;
                C[(size_t)(row + 8) * ldc + col + 1] = c[i][j][3] + b1;
            }
        }
    }
}

// ---------------------------------------------------------------------------
// Persistent recurrence, fine-grained flag sync, fragment-pipelined MMA.
// ---------------------------------------------------------------------------
__global__ __launch_bounds__(256) void rnn_persistent_kernel()
{
    extern __shared__ char smem[];
    const uint32_t smem_base = smem_u32(smem);
    const int tid  = threadIdx.x;
    const int wid  = tid >> 5;
    const int lane = tid & 31;
    const int bid  = blockIdx.x;
    const int jt   = bid >> 2;
    const int ks   = bid & 3;
    const int n0   = jt * 64;
    const int kb   = ks * 512;

    // --- stage B = G[n0:n0+64, kb:kb+512] bf16 hi+lo (once) ---
    for (int i = tid; i < 64 * 512; i += 256) {
        int n = i >> 9, k = i & 511;
        float w = g_weff[(size_t)(n0 + n) * HID + kb + k];
        __nv_bfloat16 hi = __float2bfloat16_rn(w);
        __nv_bfloat16 lo = __float2bfloat16_rn(w - __bfloat162float(hi));
        *(__nv_bfloat16*)(smem + SM_B_HI + n * 1040 + k * 2) = hi;
        *(__nv_bfloat16*)(smem + SM_B_LO + n * 1040 + k * 2) = lo;
    }
    __syncthreads();

    const uint32_t abuf_hi[2] = { smem_base + SM_A_HI0, smem_base + SM_A_HI1 };
    const uint32_t abuf_lo[2] = { smem_base + SM_A_LO0, smem_base + SM_A_LO1 };

    uint32_t cp_dst[4];
    #pragma unroll
    for (int q = 0; q < 4; q++) {
        int i = tid + q * 256;
        cp_dst[q] = (uint32_t)((i >> 3) * 144 + (i & 7) * 16);
    }

    const int mw = (wid >> 1) * 32;
    const int nw = (wid & 1) * 32;
    const uint32_t a_off0 = (uint32_t)(mw + (lane & 15)) * 144
                          + ((lane & 16) ? 16u : 0u);
    const uint32_t a_off1 = a_off0 + 16u * 144u;
    const uint32_t b_row  = (uint32_t)((lane & 7) + ((lane & 16) ? 8 : 0));
    const uint32_t b_koff = (lane & 8) ? 16u : 0u;
    const uint32_t b_off0 = (uint32_t)(nw + 0  + b_row) * 1040 + b_koff;
    const uint32_t b_off1 = (uint32_t)(nw + 16 + b_row) * 1040 + b_koff;
    const uint32_t bhi_b = smem_base + SM_B_HI;
    const uint32_t blo_b = smem_base + SM_B_LO;

    // reduce mapping: rows ks*32..+32, cols n0..+64; 8 elems/thread
    const int rrow = ks * 32 + (tid >> 3);
    const int rcol = n0 + (tid & 7) * 8;
    const int ridx = rrow * HID + rcol;

#define RN_LD_FRAGS(fa, fb, ahi_, alo_, kkv, bko_) do { \
    const uint32_t ak_ = (uint32_t)((kkv) * 32); \
    const uint32_t bk_ = (bko_) + (uint32_t)((kkv) * 32); \
    LDSM_X4((fa) + 0,  (ahi_) + a_off0 + ak_); \
    LDSM_X4((fa) + 4,  (ahi_) + a_off1 + ak_); \
    LDSM_X4((fa) + 8,  (alo_) + a_off0 + ak_); \
    LDSM_X4((fa) + 12, (alo_) + a_off1 + ak_); \
    LDSM_X4((fb) + 0,  bhi_b + b_off0 + bk_); \
    LDSM_X4((fb) + 4,  bhi_b + b_off1 + bk_); \
    LDSM_X4((fb) + 8,  blo_b + b_off0 + bk_); \
    LDSM_X4((fb) + 12, blo_b + b_off1 + bk_); \
} while (0)

    for (int t = 0; t < SEQ; t++) {
        const int p = t & 1;
        const char* __restrict__ src_hi = (const char*)g_hbf_hi[p];
        const char* __restrict__ src_lo = (const char*)g_hbf_lo[p];
        const unsigned thr_h = 4u * (unsigned)t;   // h^t ready threshold

        float c[2][4][4];
        #pragma unroll
        for (int i = 0; i < 2; i++)
            #pragma unroll
            for (int j = 0; j < 4; j++)
                #pragma unroll
                for (int q = 0; q < 4; q++) c[i][j][q] = 0.f;

        // prologue: gate chunk 0 on its producer group, then issue
        if (tid == 0) spin_ge(&g_red_cnt[ks * 8 + 0], thr_h);
        __syncthreads();
        {
            const size_t col0 = (size_t)kb * 2;
            #pragma unroll
            for (int q = 0; q < 4; q++) {
                int i = tid + q * 256;
                size_t so = (size_t)(i >> 3) * (HID * 2) + col0 + (i & 7) * 16;
                CP_ASYNC16(abuf_hi[0] + cp_dst[q], src_hi + so);
                CP_ASYNC16(abuf_lo[0] + cp_dst[q], src_lo + so);
            }
            CP_COMMIT();
        }

        #pragma unroll 1
        for (int ch = 0; ch < 8; ch++) {
            const int b = ch & 1;
            if (ch < 7 && tid == 0)
                spin_ge(&g_red_cnt[ks * 8 + ch + 1], thr_h);
            CP_WAIT0();          // chunk ch resident (only group in flight)
            __syncthreads();     // gate passed + buffer b^1 free

            if (ch < 7) {
                const size_t col = (size_t)(kb + (ch + 1) * 64) * 2;
                #pragma unroll
                for (int q = 0; q < 4; q++) {
                    int i = tid + q * 256;
                    size_t so = (size_t)(i >> 3) * (HID * 2) + col + (i & 7) * 16;
                    CP_ASYNC16(abuf_hi[b ^ 1] + cp_dst[q], src_hi + so);
                    CP_ASYNC16(abuf_lo[b ^ 1] + cp_dst[q], src_lo + so);
                }
                CP_COMMIT();
            }

            const uint32_t ahi = abuf_hi[b];
            const uint32_t alo = abuf_lo[b];
            const uint32_t bko = (uint32_t)(ch * 128);

            uint32_t fa[2][16], fb[2][16];
            RN_LD_FRAGS(fa[0], fb[0], ahi, alo, 0, bko);
            #pragma unroll
            for (int kk = 0; kk < 4; kk++) {
                const int cs = kk & 1;
                if (kk < 3) RN_LD_FRAGS(fa[cs ^ 1], fb[cs ^ 1], ahi, alo, kk + 1, bko);
                MMA_SET(c, fa[cs], fb[cs]);
            }
        }
#undef RN_LD_FRAGS

        // wait: previous step's reducers of OUR group finished reading partials
        if (tid == 0) spin_ge(&g_red_cnt[jt], thr_h);
        __syncthreads();

        // write split-K partials: warp tile 32x32 at (mw, n0+nw)
        {
            float* __restrict__ dst = g_acc[ks];
            #pragma unroll
            for (int i = 0; i < 2; i++) {
                int row = mw + i * 16 + (lane >> 2);
                #pragma unroll
                for (int j = 0; j < 4; j++) {
                    int col = n0 + nw + j * 8 + (lane & 3) * 2;
                    *(float2*)(dst + (size_t)row * HID + col) =
                        make_float2(c[i][j][0], c[i][j][1]);
                    *(float2*)(dst + (size_t)(row + 8) * HID + col) =
                        make_float2(c[i][j][2], c[i][j][3]);
                }
            }
        }
        __threadfence();
        __syncthreads();
        if (tid == 0) {
            atomicAdd(&g_mma_cnt[jt], 1u);
            spin_ge(&g_mma_cnt[jt], 4u * (unsigned)(t + 1));
        }
        __syncthreads();
        __threadfence();

        // reduce + h update for rows ks*32..+32, cols n0..+64
        {
            const float* __restrict__ xrow = g_xin + (size_t)t * BATCH * HID;
            float* __restrict__ hout = g_h[p ^ 1];
            __nv_bfloat16* __restrict__ bh_out = g_hbf_hi[p ^ 1];
            __nv_bfloat16* __restrict__ bl_out = g_hbf_lo[p ^ 1];
            #pragma unroll
            for (int q = 0; q < 2; q++) {
                int i = ridx + q * 4;
                float4 s0 = __ldcg((const float4*)(g_acc[0] + i));
                float4 s1 = __ldcg((const float4*)(g_acc[1] + i));
                float4 s2 = __ldcg((const float4*)(g_acc[2] + i));
                float4 s3 = __ldcg((const float4*)(g_acc[3] + i));
                float4 hv = __ldcg((const float4*)(g_h[p] + i));
                float4 xv = *(const float4*)(xrow + i);
                float4 o;
                o.x = hv.x + (s0.x + s1.x + s2.x + s3.x) + DT * xv.x;
                o.y = hv.y + (s0.y + s1.y + s2.y + s3.y) + DT * xv.y;
                o.z = hv.z + (s0.z + s1.z + s2.z + s3.z) + DT * xv.z;
                o.w = hv.w + (s0.w + s1.w + s2.w + s3.w) + DT * xv.w;
                *(float4*)(hout + i) = o;
                uint2 hi, lo;
                split_bf16x4(o, hi, lo);
                *(uint2*)(bh_out + i) = hi;
                *(uint2*)(bl_out + i) = lo;
            }
        }
        __threadfence();
        __syncthreads();
        if (tid == 0) atomicAdd(&g_red_cnt[jt], 1u);   // h^{t+1} cols published
    }
}

// ---------------------------------------------------------------------------
__global__ __launch_bounds__(256) void softmax_kernel(const void* __restrict__ temp_raw,
                                                      float* __restrict__ out)
{
    __shared__ float red[256];
    const int b = blockIdx.x;
    const int tid = threadIdx.x;
    const float* __restrict__ row = g_logits + (size_t)b * LDL;
    float* __restrict__ orow = out + (size_t)b * VOCAB;

    float T = 1.0f;
    if (temp_raw) {
        int iv = *(const int*)temp_raw;
        float fv = __int_as_float(iv);
        if (iv >= 1 && iv <= 1000000) T = (float)iv;
        else if (fv > 1e-8f && fv < 1e8f) T = fv;
    }
    const float invT = 1.0f / T;

    float m = -3.4e38f;
    for (int v = tid; v < VOCAB; v += 256) m = fmaxf(m, row[v]);
    red[tid] = m; __syncthreads();
    for (int s = 128; s > 0; s >>= 1) {
        if (tid < s) red[tid] = fmaxf(red[tid], red[tid + s]);
        __syncthreads();
    }
    const float mx = red[0];
    __syncthreads();

    float sum = 0.f;
    for (int v = tid; v < VOCAB; v += 256) {
        float e = expf((row[v] - mx) * invT);
        orow[v] = e;
        sum += e;
    }
    red[tid] = sum; __syncthreads();
    for (int s = 128; s > 0; s >>= 1) {
        if (tid < s) red[tid] += red[tid + s];
        __syncthreads();
    }
    const float inv = 1.0f / red[0];
    for (int v = tid; v < VOCAB; v += 256) orow[v] *= inv;
}

// ---------------------------------------------------------------------------
extern "C" void kernel_launch(void* const* d_in, const int* in_sizes, int n_in,
                              void* d_out, int out_size)
{
    const int*   ids    = (const int*)d_in[0];
    const float* h_init = (const float*)d_in[1];
    const float* emb    = (const float*)d_in[2];
    const float* W_in   = (const float*)d_in[3];
    const float* W_h    = (const float*)d_in[4];
    const float* bias   = (const float*)d_in[5];
    const float* fc_w   = (const float*)d_in[6];
    const float* fc_b   = (const float*)d_in[7];
    const void*  temp   = (n_in > 8) ? d_in[8] : nullptr;
    float*       out    = (float*)d_out;

    void *xin_ptr, *h_ptr, *logits_ptr;
    cudaGetSymbolAddress(&xin_ptr, g_xin);
    cudaGetSymbolAddress(&h_ptr, g_h);
    cudaGetSymbolAddress(&logits_ptr, g_logits);

    cudaFuncSetAttribute(rnn_persistent_kernel,
                         cudaFuncAttributeMaxDynamicSharedMemorySize, SM_TOTAL);
    cudaFuncSetAttribute(hmma_nt_kernel<true, true>,
                         cudaFuncAttributeMaxDynamicSharedMemorySize, GM_TOTAL);
    cudaFuncSetAttribute(hmma_nt_kernel<false, true>,
                         cudaFuncAttributeMaxDynamicSharedMemorySize, GM_TOTAL);

    build_weff_kernel<<<(HID * HID + 255) / 256, 256>>>(W_h);
    init_h_kernel<<<(BATCH * HID + 255) / 256, 256>>>(h_init);

    // xin = gather(emb, ids) @ W_in^T + bias : M=131072, N=2048, K=512 (HMMA)
    hmma_nt_kernel<true, true><<<dim3(HID / 64, (SEQ * BATCH) / 128), 256, GM_TOTAL>>>(
        emb, ids, W_in, bias, (float*)xin_ptr, HID, EMB, HID);

    // 1024 Euler steps, persistent flag-synced pipelined HMMA kernel
    rnn_persistent_kernel<<<NCTA, 256, SM_TOTAL>>>();

    // logits = h_final @ fc_w^T + fc_b : M=128, N=50257, K=2048 (HMMA)
    hmma_nt_kernel<false, true><<<dim3((VOCAB + 63) / 64, 1), 256, GM_TOTAL>>>(
        (const float*)h_ptr, nullptr, fc_w, fc_b, (float*)logits_ptr,
        VOCAB, HID, LDL);

    softmax_kernel<<<BATCH, 256>>>(temp, out);
}

// round 16
// speedup vs baseline: 1.0459x; 1.0459x over previous
#include <cuda_runtime.h>
#include <cuda_bf16.h>
#include <stdint.h>
#include <math.h>

// ---------------------------------------------------------------------------
// CharRNN on GB300 (sm_103 baseline PTX -> warp HMMA mma.sync bf16x3).
// R15: break MMA accumulator RAW chains. R13/R15 profiles showed tensor
// stuck at ~32% with asm-volatile MMAs forcing an order where each
// accumulator is rewritten with only 1 intervening MMA (stall ~= lat-2rt
// every other MMA, unhidable at 2 warps/SMSP). MMA_SET is now pass-major
// (8 independent accumulators between reuses) and MMA asm is non-volatile
// so ptxas can schedule.
// h_{t+1} = h_t + (h_t @ G^T) + dt*xin[t],  G = dt*(Wh - Wh^T - diff*I)
// ---------------------------------------------------------------------------

#define SEQ    1024
#define BATCH  128
#define HID    2048
#define EMB    512
#define VOCAB  50257
#define LDL    50260
#define DT     0.01f
#define DIFF   0.001f
#define NCTA   128
#define NGRP   32

// recurrence smem (bytes)
#define SM_B_HI   0
#define SM_B_LO   66560
#define SM_A_HI0  133120
#define SM_A_LO0  151552
#define SM_A_HI1  169984
#define SM_A_LO1  188416
#define SM_TOTAL  206848

// generic hmma gemm smem
#define GM_A_HI  0
#define GM_A_LO  34816
#define GM_B_HI  69632
#define GM_B_LO  87040
#define GM_TOTAL 104448

// scratch
__device__ float g_xin[(size_t)SEQ * BATCH * HID];
__device__ float g_weff[(size_t)HID * HID];          // G = dt*(Wh-Wh^T-diff I)
__device__ float g_h[2][BATCH * HID];                // fp32 carry (ping-pong)
__device__ __nv_bfloat16 g_hbf_hi[2][BATCH * HID];   // bf16 hi of h
__device__ __nv_bfloat16 g_hbf_lo[2][BATCH * HID];   // bf16 lo of h
__device__ float g_acc[4][BATCH * HID];              // split-K partials
__device__ float g_logits[(size_t)BATCH * LDL];
__device__ unsigned g_mma_cnt[NGRP];                 // partials of group ready
__device__ unsigned g_red_cnt[NGRP];                 // h cols of group ready

// ---------------------------------------------------------------------------
__device__ __forceinline__ uint32_t smem_u32(const void* p) {
    uint32_t a;
    asm("{ .reg .u64 t; cvta.to.shared.u64 t, %1; cvt.u32.u64 %0, t; }"
        : "=r"(a) : "l"(p));
    return a;
}

#define LDSM_X4(r, addr) \
    asm volatile("ldmatrix.sync.aligned.m8n8.x4.shared.b16 {%0,%1,%2,%3}, [%4];" \
        : "=r"((r)[0]), "=r"((r)[1]), "=r"((r)[2]), "=r"((r)[3]) \
        : "r"(addr))

// NOTE: non-volatile — pure register computation; lets ptxas schedule MMAs.
#define MMA16816(c, a, b) \
    asm("mma.sync.aligned.m16n8k16.row.col.f32.bf16.bf16.f32 " \
        "{%0,%1,%2,%3}, {%4,%5,%6,%7}, {%8,%9}, {%0,%1,%2,%3};" \
        : "+f"((c)[0]), "+f"((c)[1]), "+f"((c)[2]), "+f"((c)[3]) \
        : "r"((a)[0]), "r"((a)[1]), "r"((a)[2]), "r"((a)[3]), \
          "r"((b)[0]), "r"((b)[1]))

#define CP_ASYNC16(dst, src) \
    asm volatile("cp.async.cg.shared.global [%0], [%1], 16;" \
        :: "r"(dst), "l"(src) : "memory")
#define CP_COMMIT() asm volatile("cp.async.commit_group;" ::: "memory")
#define CP_WAIT0()  asm volatile("cp.async.wait_group 0;" ::: "memory")

__device__ __forceinline__ void spin_ge(const unsigned* p, unsigned thr) {
    while (*(volatile const unsigned*)p < thr) { }
}

// fp32 -> bf16 hi/lo pair (packed as 2 x uint32 of bf16x2)
__device__ __forceinline__ void split_bf16x4(float4 v, uint2& hi, uint2& lo) {
    __nv_bfloat162 h01 = __float22bfloat162_rn(make_float2(v.x, v.y));
    __nv_bfloat162 h23 = __float22bfloat162_rn(make_float2(v.z, v.w));
    float2 f01 = __bfloat1622float2(h01);
    float2 f23 = __bfloat1622float2(h23);
    __nv_bfloat162 l01 = __float22bfloat162_rn(make_float2(v.x - f01.x, v.y - f01.y));
    __nv_bfloat162 l23 = __float22bfloat162_rn(make_float2(v.z - f23.x, v.w - f23.y));
    hi = make_uint2(*(uint32_t*)&h01, *(uint32_t*)&h23);
    lo = make_uint2(*(uint32_t*)&l01, *(uint32_t*)&l23);
}

// bf16x3 MMAs for one (m32 x n32) accumulator set, PASS-MAJOR order:
// all 8 independent (i,j) accumulators per product term before reuse.
// fa: [ah0 ah1 al0 al1] x4 regs; fb: [bh(8) bl(8)].
#define MMA_SET(cacc, fa, fb) do { \
    _Pragma("unroll") \
    for (int j_ = 0; j_ < 4; j_++) {                      /* pass hi*hi */ \
        MMA16816((cacc)[0][j_], (fa) + 0,  (fb) + j_ * 2); \
        MMA16816((cacc)[1][j_], (fa) + 4,  (fb) + j_ * 2); \
    } \
    _Pragma("unroll") \
    for (int j_ = 0; j_ < 4; j_++) {                      /* pass hi*lo */ \
        MMA16816((cacc)[0][j_], (fa) + 0,  (fb) + 8 + j_ * 2); \
        MMA16816((cacc)[1][j_], (fa) + 4,  (fb) + 8 + j_ * 2); \
    } \
    _Pragma("unroll") \
    for (int j_ = 0; j_ < 4; j_++) {                      /* pass lo*hi */ \
        MMA16816((cacc)[0][j_], (fa) + 8,  (fb) + j_ * 2); \
        MMA16816((cacc)[1][j_], (fa) + 12, (fb) + j_ * 2); \
    } \
} while (0)

// ---------------------------------------------------------------------------
__global__ void build_weff_kernel(const float* __restrict__ Wh) {
    int idx = blockIdx.x * blockDim.x + threadIdx.x;
    if (idx < HID * HID) {
        int i = idx / HID, j = idx % HID;
        float v = Wh[idx] - Wh[j * HID + i];
        if (i == j) v -= DIFF;
        g_weff[idx] = DT * v;
    }
}

__global__ void init_h_kernel(const float* __restrict__ h0) {
    int i = blockIdx.x * blockDim.x + threadIdx.x;
    if (i < NGRP) { g_mma_cnt[i] = 0u; g_red_cnt[i] = 0u; }  // replay reset
    if (i < BATCH * HID) {
        float v = h0[i];
        g_h[0][i] = v;
        __nv_bfloat16 hi = __float2bfloat16_rn(v);
        g_hbf_hi[0][i] = hi;
        g_hbf_lo[0][i] = __float2bfloat16_rn(v - __bfloat162float(hi));
    }
}

// ---------------------------------------------------------------------------
// Generic NT HMMA GEMM (bf16x3), pass-major MMA order.
// ---------------------------------------------------------------------------
template <bool GATHER, bool HAS_BIAS>
__global__ __launch_bounds__(256) void hmma_nt_kernel(
    const float* __restrict__ A, const int* __restrict__ gidx,
    const float* __restrict__ B, const float* __restrict__ bias,
    float* __restrict__ C, int N, int K, int ldc)
{
    extern __shared__ char sm[];
    const uint32_t smb = smem_u32(sm);
    const int tid = threadIdx.x, wid = tid >> 5, lane = tid & 31;
    const int m0 = blockIdx.y * 128;
    const int n0 = blockIdx.x * 64;

    const int mw = (wid >> 1) * 32;
    const int nw = (wid & 1) * 32;
    const uint32_t a_off0 = (uint32_t)(mw + (lane & 15)) * 272
                          + ((lane & 16) ? 16u : 0u);
    const uint32_t a_off1 = a_off0 + 16u * 272u;
    const uint32_t b_row  = (uint32_t)((lane & 7) + ((lane & 16) ? 8 : 0));
    const uint32_t b_koff = (lane & 8) ? 16u : 0u;
    const uint32_t b_off0 = (uint32_t)(nw + b_row) * 272 + b_koff;
    const uint32_t b_off1 = (uint32_t)(nw + 16 + b_row) * 272 + b_koff;

    float c[2][4][4];
    #pragma unroll
    for (int i = 0; i < 2; i++)
        #pragma unroll
        for (int j = 0; j < 4; j++)
            #pragma unroll
            for (int q = 0; q < 4; q++) c[i][j][q] = 0.f;

#define GM_LD_FRAGS(fa, fb, kkv) do { \
    const uint32_t ak_ = (uint32_t)((kkv) * 32); \
    LDSM_X4((fa) + 0,  smb + GM_A_HI + a_off0 + ak_); \
    LDSM_X4((fa) + 4,  smb + GM_A_HI + a_off1 + ak_); \
    LDSM_X4((fa) + 8,  smb + GM_A_LO + a_off0 + ak_); \
    LDSM_X4((fa) + 12, smb + GM_A_LO + a_off1 + ak_); \
    LDSM_X4((fb) + 0,  smb + GM_B_HI + b_off0 + ak_); \
    LDSM_X4((fb) + 4,  smb + GM_B_HI + b_off1 + ak_); \
    LDSM_X4((fb) + 8,  smb + GM_B_LO + b_off0 + ak_); \
    LDSM_X4((fb) + 12, smb + GM_B_LO + b_off1 + ak_); \
} while (0)

    for (int kc = 0; kc < K; kc += 128) {
        __syncthreads();   // previous chunk fully consumed
        // stage A chunk: 128 rows x 128 cols
        for (int i = tid; i < 4096; i += 256) {
            int r = i >> 5, c4 = (i & 31) << 2;
            const float* arow = GATHER
                ? A + (size_t)__ldg(gidx + m0 + r) * K
                : A + (size_t)(m0 + r) * K;
            float4 v = *(const float4*)(arow + kc + c4);
            uint2 hi, lo;
            split_bf16x4(v, hi, lo);
            uint32_t off = (uint32_t)(r * 272 + c4 * 2);
            *(uint2*)(sm + GM_A_HI + off) = hi;
            *(uint2*)(sm + GM_A_LO + off) = lo;
        }
        // stage B chunk: 64 rows x 128 cols, zero-pad n >= N
        for (int i = tid; i < 2048; i += 256) {
            int r = i >> 5, c4 = (i & 31) << 2;
            int n = n0 + r;
            float4 v = (n < N) ? *(const float4*)(B + (size_t)n * K + kc + c4)
                               : make_float4(0.f, 0.f, 0.f, 0.f);
            uint2 hi, lo;
            split_bf16x4(v, hi, lo);
            uint32_t off = (uint32_t)(r * 272 + c4 * 2);
            *(uint2*)(sm + GM_B_HI + off) = hi;
            *(uint2*)(sm + GM_B_LO + off) = lo;
        }
        __syncthreads();

        uint32_t fa[16], fb[16];
        #pragma unroll
        for (int kk = 0; kk < 8; kk++) {
            GM_LD_FRAGS(fa, fb, kk);
            MMA_SET(c, fa, fb);
        }
    }
#undef GM_LD_FRAGS

    // epilogue: bias + guarded store
    #pragma unroll
    for (int i = 0; i < 2; i++) {
        int row = m0 + mw + i * 16 + (lane >> 2);
        #pragma unroll
        for (int j = 0; j < 4; j++) {
            int col = n0 + nw + j * 8 + (lane & 3) * 2;
            if (col < N) {
                float b0 = HAS_BIAS ? bias[col] : 0.f;
                C[(size_t)row * ldc + col]       = c[i][j][0] + b0;
                C[(size_t)(row + 8) * ldc + col] = c[i][j][2] + b0;
            }
            if (col + 1 < N) {
                float b1 = HAS_BIAS ? bias[col + 1] : 0.f;
                C[(size_t)row * ldc + col + 1]       = c[i][j][1] + b1;
                C[(size_t)(row + 8) * ldc + col + 1] = c[i][j][3] + b1;
            }
        }
    }
}

// ---------------------------------------------------------------------------
// Persistent recurrence, fine-grained flag sync, pass-major MMA order.
// ---------------------------------------------------------------------------
__global__ __launch_bounds__(256) void rnn_persistent_kernel()
{
    extern __shared__ char smem[];
    const uint32_t smem_base = smem_u32(smem);
    const int tid  = threadIdx.x;
    const int wid  = tid >> 5;
    const int lane = tid & 31;
    const int bid  = blockIdx.x;
    const int jt   = bid >> 2;
    const int ks   = bid & 3;
    const int n0   = jt * 64;
    const int kb   = ks * 512;

    // --- stage B = G[n0:n0+64, kb:kb+512] bf16 hi+lo (once) ---
    for (int i = tid; i < 64 * 512; i += 256) {
        int n = i >> 9, k = i & 511;
        float w = g_weff[(size_t)(n0 + n) * HID + kb + k];
        __nv_bfloat16 hi = __float2bfloat16_rn(w);
        __nv_bfloat16 lo = __float2bfloat16_rn(w - __bfloat162float(hi));
        *(__nv_bfloat16*)(smem + SM_B_HI + n * 1040 + k * 2) = hi;
        *(__nv_bfloat16*)(smem + SM_B_LO + n * 1040 + k * 2) = lo;
    }
    __syncthreads();

    const uint32_t abuf_hi[2] = { smem_base + SM_A_HI0, smem_base + SM_A_HI1 };
    const uint32_t abuf_lo[2] = { smem_base + SM_A_LO0, smem_base + SM_A_LO1 };

    uint32_t cp_dst[4];
    #pragma unroll
    for (int q = 0; q < 4; q++) {
        int i = tid + q * 256;
        cp_dst[q] = (uint32_t)((i >> 3) * 144 + (i & 7) * 16);
    }

    const int mw = (wid >> 1) * 32;
    const int nw = (wid & 1) * 32;
    const uint32_t a_off0 = (uint32_t)(mw + (lane & 15)) * 144
                          + ((lane & 16) ? 16u : 0u);
    const uint32_t a_off1 = a_off0 + 16u * 144u;
    const uint32_t b_row  = (uint32_t)((lane & 7) + ((lane & 16) ? 8 : 0));
    const uint32_t b_koff = (lane & 8) ? 16u : 0u;
    const uint32_t b_off0 = (uint32_t)(nw + 0  + b_row) * 1040 + b_koff;
    const uint32_t b_off1 = (uint32_t)(nw + 16 + b_row) * 1040 + b_koff;
    const uint32_t bhi_b = smem_base + SM_B_HI;
    const uint32_t blo_b = smem_base + SM_B_LO;

    // reduce mapping: rows ks*32..+32, cols n0..+64; 8 elems/thread
    const int rrow = ks * 32 + (tid >> 3);
    const int rcol = n0 + (tid & 7) * 8;
    const int ridx = rrow * HID + rcol;

#define RN_LD_FRAGS(fa, fb, ahi_, alo_, kkv, bko_) do { \
    const uint32_t ak_ = (uint32_t)((kkv) * 32); \
    const uint32_t bk_ = (bko_) + (uint32_t)((kkv) * 32); \
    LDSM_X4((fa) + 0,  (ahi_) + a_off0 + ak_); \
    LDSM_X4((fa) + 4,  (ahi_) + a_off1 + ak_); \
    LDSM_X4((fa) + 8,  (alo_) + a_off0 + ak_); \
    LDSM_X4((fa) + 12, (alo_) + a_off1 + ak_); \
    LDSM_X4((fb) + 0,  bhi_b + b_off0 + bk_); \
    LDSM_X4((fb) + 4,  bhi_b + b_off1 + bk_); \
    LDSM_X4((fb) + 8,  blo_b + b_off0 + bk_); \
    LDSM_X4((fb) + 12, blo_b + b_off1 + bk_); \
} while (0)

    for (int t = 0; t < SEQ; t++) {
        const int p = t & 1;
        const char* __restrict__ src_hi = (const char*)g_hbf_hi[p];
        const char* __restrict__ src_lo = (const char*)g_hbf_lo[p];
        const unsigned thr_h = 4u * (unsigned)t;   // h^t ready threshold

        float c[2][4][4];
        #pragma unroll
        for (int i = 0; i < 2; i++)
            #pragma unroll
            for (int j = 0; j < 4; j++)
                #pragma unroll
                for (int q = 0; q < 4; q++) c[i][j][q] = 0.f;

        // prologue: gate chunk 0 on its producer group, then issue
        if (tid == 0) spin_ge(&g_red_cnt[ks * 8 + 0], thr_h);
        __syncthreads();
        {
            const size_t col0 = (size_t)kb * 2;
            #pragma unroll
            for (int q = 0; q < 4; q++) {
                int i = tid + q * 256;
                size_t so = (size_t)(i >> 3) * (HID * 2) + col0 + (i & 7) * 16;
                CP_ASYNC16(abuf_hi[0] + cp_dst[q], src_hi + so);
                CP_ASYNC16(abuf_lo[0] + cp_dst[q], src_lo + so);
            }
            CP_COMMIT();
        }

        #pragma unroll 1
        for (int ch = 0; ch < 8; ch++) {
            const int b = ch & 1;
            if (ch < 7 && tid == 0)
                spin_ge(&g_red_cnt[ks * 8 + ch + 1], thr_h);
            CP_WAIT0();          // chunk ch resident (only group in flight)
            __syncthreads();     // gate passed + buffer b^1 free

            if (ch < 7) {
                const size_t col = (size_t)(kb + (ch + 1) * 64) * 2;
                #pragma unroll
                for (int q = 0; q < 4; q++) {
                    int i = tid + q * 256;
                    size_t so = (size_t)(i >> 3) * (HID * 2) + col + (i & 7) * 16;
                    CP_ASYNC16(abuf_hi[b ^ 1] + cp_dst[q], src_hi + so);
                    CP_ASYNC16(abuf_lo[b ^ 1] + cp_dst[q], src_lo + so);
                }
                CP_COMMIT();
            }

            const uint32_t ahi = abuf_hi[b];
            const uint32_t alo = abuf_lo[b];
            const uint32_t bko = (uint32_t)(ch * 128);

            uint32_t fa[16], fb[16];
            #pragma unroll
            for (int kk = 0; kk < 4; kk++) {
                RN_LD_FRAGS(fa, fb, ahi, alo, kk, bko);
                MMA_SET(c, fa, fb);
            }
        }
#undef RN_LD_FRAGS

        // wait: previous step's reducers of OUR group finished reading partials
        if (tid == 0) spin_ge(&g_red_cnt[jt], thr_h);
        __syncthreads();

        // write split-K partials: warp tile 32x32 at (mw, n0+nw)
        {
            float* __restrict__ dst = g_acc[ks];
            #pragma unroll
            for (int i = 0; i < 2; i++) {
                int row = mw + i * 16 + (lane >> 2);
                #pragma unroll
                for (int j = 0; j < 4; j++) {
                    int col = n0 + nw + j * 8 + (lane & 3) * 2;
                    *(float2*)(dst + (size_t)row * HID + col) =
                        make_float2(c[i][j][0], c[i][j][1]);
                    *(float2*)(dst + (size_t)(row + 8) * HID + col) =
                        make_float2(c[i][j][2], c[i][j][3]);
                }
            }
        }
        __threadfence();
        __syncthreads();
        if (tid == 0) {
            atomicAdd(&g_mma_cnt[jt], 1u);
            spin_ge(&g_mma_cnt[jt], 4u * (unsigned)(t + 1));
        }
        __syncthreads();
        __threadfence();

        // reduce + h update for rows ks*32..+32, cols n0..+64
        {
            const float* __restrict__ xrow = g_xin + (size_t)t * BATCH * HID;
            float* __restrict__ hout = g_h[p ^ 1];
            __nv_bfloat16* __restrict__ bh_out = g_hbf_hi[p ^ 1];
            __nv_bfloat16* __restrict__ bl_out = g_hbf_lo[p ^ 1];
            #pragma unroll
            for (int q = 0; q < 2; q++) {
                int i = ridx + q * 4;
                float4 s0 = __ldcg((const float4*)(g_acc[0] + i));
                float4 s1 = __ldcg((const float4*)(g_acc[1] + i));
                float4 s2 = __ldcg((const float4*)(g_acc[2] + i));
                float4 s3 = __ldcg((const float4*)(g_acc[3] + i));
                float4 hv = __ldcg((const float4*)(g_h[p] + i));
                float4 xv = *(const float4*)(xrow + i);
                float4 o;
                o.x = hv.x + (s0.x + s1.x + s2.x + s3.x) + DT * xv.x;
                o.y = hv.y + (s0.y + s1.y + s2.y + s3.y) + DT * xv.y;
                o.z = hv.z + (s0.z + s1.z + s2.z + s3.z) + DT * xv.z;
                o.w = hv.w + (s0.w + s1.w + s2.w + s3.w) + DT * xv.w;
                *(float4*)(hout + i) = o;
                uint2 hi, lo;
                split_bf16x4(o, hi, lo);
                *(uint2*)(bh_out + i) = hi;
                *(uint2*)(bl_out + i) = lo;
            }
        }
        __threadfence();
        __syncthreads();
        if (tid == 0) atomicAdd(&g_red_cnt[jt], 1u);   // h^{t+1} cols published
    }
}

// ---------------------------------------------------------------------------
__global__ __launch_bounds__(256) void softmax_kernel(const void* __restrict__ temp_raw,
                                                      float* __restrict__ out)
{
    __shared__ float red[256];
    const int b = blockIdx.x;
    const int tid = threadIdx.x;
    const float* __restrict__ row = g_logits + (size_t)b * LDL;
    float* __restrict__ orow = out + (size_t)b * VOCAB;

    float T = 1.0f;
    if (temp_raw) {
        int iv = *(const int*)temp_raw;
        float fv = __int_as_float(iv);
        if (iv >= 1 && iv <= 1000000) T = (float)iv;
        else if (fv > 1e-8f && fv < 1e8f) T = fv;
    }
    const float invT = 1.0f / T;

    float m = -3.4e38f;
    for (int v = tid; v < VOCAB; v += 256) m = fmaxf(m, row[v]);
    red[tid] = m; __syncthreads();
    for (int s = 128; s > 0; s >>= 1) {
        if (tid < s) red[tid] = fmaxf(red[tid], red[tid + s]);
        __syncthreads();
    }
    const float mx = red[0];
    __syncthreads();

    float sum = 0.f;
    for (int v = tid; v < VOCAB; v += 256) {
        float e = expf((row[v] - mx) * invT);
        orow[v] = e;
        sum += e;
    }
    red[tid] = sum; __syncthreads();
    for (int s = 128; s > 0; s >>= 1) {
        if (tid < s) red[tid] += red[tid + s];
        __syncthreads();
    }
    const float inv = 1.0f / red[0];
    for (int v = tid; v < VOCAB; v += 256) orow[v] *= inv;
}

// ---------------------------------------------------------------------------
extern "C" void kernel_launch(void* const* d_in, const int* in_sizes, int n_in,
                              void* d_out, int out_size)
{
    const int*   ids    = (const int*)d_in[0];
    const float* h_init = (const float*)d_in[1];
    const float* emb    = (const float*)d_in[2];
    const float* W_in   = (const float*)d_in[3];
    const float* W_h    = (const float*)d_in[4];
    const float* bias   = (const float*)d_in[5];
    const float* fc_w   = (const float*)d_in[6];
    const float* fc_b   = (const float*)d_in[7];
    const void*  temp   = (n_in > 8) ? d_in[8] : nullptr;
    float*       out    = (float*)d_out;

    void *xin_ptr, *h_ptr, *logits_ptr;
    cudaGetSymbolAddress(&xin_ptr, g_xin);
    cudaGetSymbolAddress(&h_ptr, g_h);
    cudaGetSymbolAddress(&logits_ptr, g_logits);

    cudaFuncSetAttribute(rnn_persistent_kernel,
                         cudaFuncAttributeMaxDynamicSharedMemorySize, SM_TOTAL);
    cudaFuncSetAttribute(hmma_nt_kernel<true, true>,
                         cudaFuncAttributeMaxDynamicSharedMemorySize, GM_TOTAL);
    cudaFuncSetAttribute(hmma_nt_kernel<false, true>,
                         cudaFuncAttributeMaxDynamicSharedMemorySize, GM_TOTAL);

    build_weff_kernel<<<(HID * HID + 255) / 256, 256>>>(W_h);
    init_h_kernel<<<(BATCH * HID + 255) / 256, 256>>>(h_init);

    // xin = gather(emb, ids) @ W_in^T + bias : M=131072, N=2048, K=512 (HMMA)
    hmma_nt_kernel<true, true><<<dim3(HID / 64, (SEQ * BATCH) / 128), 256, GM_TOTAL>>>(
        emb, ids, W_in, bias, (float*)xin_ptr, HID, EMB, HID);

    // 1024 Euler steps, persistent flag-synced HMMA kernel
    rnn_persistent_kernel<<<NCTA, 256, SM_TOTAL>>>();

    // logits = h_final @ fc_w^T + fc_b : M=128, N=50257, K=2048 (HMMA)
    hmma_nt_kernel<false, true><<<dim3((VOCAB + 63) / 64, 1), 256, GM_TOTAL>>>(
        (const float*)h_ptr, nullptr, fc_w, fc_b, (float*)logits_ptr,
        VOCAB, HID, LDL);

    softmax_kernel<<<BATCH, 256>>>(temp, out);
}